// round 15
// baseline (speedup 1.0000x reference)
#include <cuda_runtime.h>
#include <cstdint>

#define NMAX 20000
#define EMAX 320000
#define CS   128           // LSTM pipeline chunk (steps)
#define NCHMAX ((NMAX + CS - 1) / CS)

typedef unsigned long long ull;

// ---------------- scratch (static device arrays; no allocation) ----------------
__device__ float g_dinv[NMAX];
__device__ float g_xw  [NMAX * 128];
__device__ float g_agg [NMAX * 128];
__device__ float g_h   [NMAX * 128];
__device__ float g_hs0 [NMAX * 128];
__device__ float g_hs1 [NMAX * 128];
__device__ float g_gx  [NMAX * 512];   // layer0 gate inputs (worker CTA role2)
__device__ float g_gx1 [NMAX * 512];   // layer1 gate inputs (worker CTA role3)
__device__ int   g_src [EMAX];
__device__ int   g_dst [EMAX];
__device__ int   g_flag[1];
__device__ int   g_prog0;              // layer0 published step count
__device__ int   g_rdy0[NCHMAX];       // per-chunk gx0 ready flags
__device__ int   g_rdy [NCHMAX];       // per-chunk gx1 ready flags

// ---------------- helpers ----------------
__device__ __forceinline__ ull ffma2(ull a, ull b, ull c) {
    ull d;
    asm("fma.rn.f32x2 %0, %1, %2, %3;" : "=l"(d) : "l"(a), "l"(b), "l"(c));
    return d;
}
__device__ __forceinline__ ull addp(ull a, ull b) {
    ull d;
    asm("add.rn.f32x2 %0, %1, %2;" : "=l"(d) : "l"(a), "l"(b));
    return d;
}
__device__ __forceinline__ float2 upk(ull a) {
    float2 r;
    asm("mov.b64 {%0, %1}, %2;" : "=f"(r.x), "=f"(r.y) : "l"(a));
    return r;
}
__device__ __forceinline__ float fast_sig(float x) {
    float e; asm("ex2.approx.f32 %0, %1;" : "=f"(e) : "f"(-1.4426950408889634f * x));
    float r; asm("rcp.approx.f32 %0, %1;" : "=f"(r) : "f"(1.0f + e));
    return r;
}
__device__ __forceinline__ float fast_tanh(float x) {
    float e; asm("ex2.approx.f32 %0, %1;" : "=f"(e) : "f"(-2.8853900817779268f * x));
    float r; asm("rcp.approx.f32 %0, %1;" : "=f"(r) : "f"(1.0f + e));
    return fmaf(2.0f, r, -1.0f);
}
__device__ __forceinline__ int ld_acq(const int* p) {
    int v; asm volatile("ld.acquire.gpu.b32 %0, [%1];" : "=r"(v) : "l"(p)); return v;
}
__device__ __forceinline__ void st_rel(int* p, int v) {
    asm volatile("st.release.gpu.b32 [%0], %1;" :: "l"(p), "r"(v));
}

// ---------------- edge index dtype detect + normalize ----------------
__global__ void k_detect(const int* ei) {
    if (threadIdx.x == 0 && blockIdx.x == 0) {
        int nz = 0;
        for (int i = 0; i < 128; i++) nz += (ei[2 * i + 1] != 0);
        g_flag[0] = (nz == 0) ? 1 : 0;
    }
}

__global__ void k_convert(const void* ei, int E, int N) {
    int e = blockIdx.x * blockDim.x + threadIdx.x;
    if (e >= E) return;
    int s, d;
    if (g_flag[0]) {
        const long long* p = (const long long*)ei;
        s = (int)p[e]; d = (int)p[E + e];
    } else {
        const int* p = (const int*)ei;
        s = p[e]; d = p[E + e];
    }
    s = min(max(s, 0), N - 1);
    d = min(max(d, 0), N - 1);
    g_src[e] = s; g_dst[e] = d;
}

// ---------------- GCN: init (+ pipeline counter reset) ----------------
__global__ void k_init(int N) {
    int i = blockIdx.x * blockDim.x + threadIdx.x;
    if (i < N * 128) g_agg[i] = 0.0f;
    if (i < N)       g_dinv[i] = 1.0f;
    if (i == 0)      g_prog0 = 0;
    if (i < NCHMAX)  { g_rdy[i] = 0; g_rdy0[i] = 0; }
}

__global__ void k_deg(int E) {
    int e = blockIdx.x * blockDim.x + threadIdx.x;
    if (e < E) atomicAdd(&g_dinv[g_dst[e]], 1.0f);
}

__global__ void k_rsqrt(int N) {
    int i = blockIdx.x * blockDim.x + threadIdx.x;
    if (i < N) g_dinv[i] = rsqrtf(g_dinv[i]);
}

// ---------------- generic K=128 GEMM (GCN convs) ----------------
template <int TRANSB>
__global__ void __launch_bounds__(256) k_gemm(
    const float* __restrict__ A, const float* __restrict__ B,
    const float* __restrict__ bias1, const float* __restrict__ bias2,
    float* __restrict__ C, int M, int NC)
{
    __shared__ __align__(16) float As[16][64];
    __shared__ __align__(16) float Bs[16][64];
    int tid = threadIdx.x;
    int m0 = blockIdx.y * 64, n0 = blockIdx.x * 64;
    int tx = tid & 15, ty = tid >> 4;
    float acc[4][4];
#pragma unroll
    for (int i = 0; i < 4; i++)
#pragma unroll
        for (int j = 0; j < 4; j++) acc[i][j] = 0.0f;

    int lm = tid >> 2, lq = tid & 3;

    for (int k0 = 0; k0 < 128; k0 += 16) {
        float4 av = make_float4(0.f, 0.f, 0.f, 0.f);
        if (m0 + lm < M)
            av = *(const float4*)(A + (size_t)(m0 + lm) * 128 + k0 + lq * 4);
        As[lq * 4 + 0][lm] = av.x;
        As[lq * 4 + 1][lm] = av.y;
        As[lq * 4 + 2][lm] = av.z;
        As[lq * 4 + 3][lm] = av.w;

        if (TRANSB) {
            float4 bv = *(const float4*)(B + (size_t)(n0 + lm) * 128 + k0 + lq * 4);
            Bs[lq * 4 + 0][lm] = bv.x;
            Bs[lq * 4 + 1][lm] = bv.y;
            Bs[lq * 4 + 2][lm] = bv.z;
            Bs[lq * 4 + 3][lm] = bv.w;
        } else {
            int bk = tid >> 4, bn = tid & 15;
            float4 bv = *(const float4*)(B + (size_t)(k0 + bk) * NC + n0 + bn * 4);
            *(float4*)&Bs[bk][bn * 4] = bv;
        }
        __syncthreads();

#pragma unroll
        for (int k = 0; k < 16; k++) {
            float4 a = *(const float4*)&As[k][ty * 4];
            float4 b = *(const float4*)&Bs[k][tx * 4];
            acc[0][0] += a.x * b.x; acc[0][1] += a.x * b.y; acc[0][2] += a.x * b.z; acc[0][3] += a.x * b.w;
            acc[1][0] += a.y * b.x; acc[1][1] += a.y * b.y; acc[1][2] += a.y * b.z; acc[1][3] += a.y * b.w;
            acc[2][0] += a.z * b.x; acc[2][1] += a.z * b.y; acc[2][2] += a.z * b.z; acc[2][3] += a.z * b.w;
            acc[3][0] += a.w * b.x; acc[3][1] += a.w * b.y; acc[3][2] += a.w * b.z; acc[3][3] += a.w * b.w;
        }
        __syncthreads();
    }

    float bb[4] = {0.f, 0.f, 0.f, 0.f};
    if (bias1) {
#pragma unroll
        for (int j = 0; j < 4; j++) bb[j] += bias1[n0 + tx * 4 + j];
    }
    if (bias2) {
#pragma unroll
        for (int j = 0; j < 4; j++) bb[j] += bias2[n0 + tx * 4 + j];
    }
#pragma unroll
    for (int i = 0; i < 4; i++) {
        int m = m0 + ty * 4 + i;
        if (m < M) {
#pragma unroll
            for (int j = 0; j < 4; j++)
                C[(size_t)m * NC + n0 + tx * 4 + j] = acc[i][j] + bb[j];
        }
    }
}

// ---------------- GCN scatter (atomic aggregate) ----------------
__global__ void k_scatter(const float* __restrict__ xw, int E) {
    int idx = blockIdx.x * blockDim.x + threadIdx.x;
    int e = idx >> 5, lane = idx & 31;
    if (e >= E) return;
    int s = g_src[e], d = g_dst[e];
    float nrm = g_dinv[s] * g_dinv[d];
    float4 v = *(const float4*)(xw + (size_t)s * 128 + lane * 4);
    float* out = g_agg + (size_t)d * 128 + lane * 4;
    atomicAdd(out + 0, v.x * nrm);
    atomicAdd(out + 1, v.y * nrm);
    atomicAdd(out + 2, v.z * nrm);
    atomicAdd(out + 3, v.w * nrm);
}

__global__ void k_finish(const float* __restrict__ xw, const float* __restrict__ bias,
                         float* __restrict__ out, int N, int relu) {
    int idx = blockIdx.x * blockDim.x + threadIdx.x;
    if (idx >= N * 128) return;
    int i = idx >> 7, c = idx & 127;
    float di = g_dinv[i];
    float v = g_agg[idx] + xw[idx] * di * di + bias[c];
    if (relu) v = fmaxf(v, 0.0f);
    out[idx] = v;
    g_agg[idx] = 0.0f;
}

// ---------------- worker GEMM for one chunk: C[Mc,512] = A[Mc,128] @ B[512,128]^T + b ---
// 512 threads = 2 groups of 256; both groups iterate identical tile counts (barrier-safe).
__device__ void gemm_chunk(const float* __restrict__ A, int Mc,
                           const float* __restrict__ B,
                           const float* __restrict__ bi1, const float* __restrict__ bi2,
                           float* __restrict__ C, float* smem)
{
    int tid = threadIdx.x;
    int grp = tid >> 8, gt = tid & 255;
    float* As = smem + grp * 2048;     // [16][64]
    float* Bs = As + 1024;             // [16][64]
    int tx = gt & 15, ty = gt >> 4;
    int lm = gt >> 2, lq = gt & 3;
    int mt = (Mc + 63) >> 6;
    int nTiles = mt * 8;               // always even (8 or 16)

    for (int p = 0; p < nTiles; p += 2) {
        int idx = p + grp;
        int m0 = (idx >> 3) << 6, n0 = (idx & 7) << 6;
        float acc[4][4];
#pragma unroll
        for (int i = 0; i < 4; i++)
#pragma unroll
            for (int j = 0; j < 4; j++) acc[i][j] = 0.0f;

        for (int k0 = 0; k0 < 128; k0 += 16) {
            float4 av = make_float4(0.f, 0.f, 0.f, 0.f);
            if (m0 + lm < Mc)
                av = *(const float4*)(A + (size_t)(m0 + lm) * 128 + k0 + lq * 4);
            As[(lq * 4 + 0) * 64 + lm] = av.x;
            As[(lq * 4 + 1) * 64 + lm] = av.y;
            As[(lq * 4 + 2) * 64 + lm] = av.z;
            As[(lq * 4 + 3) * 64 + lm] = av.w;

            float4 bv = *(const float4*)(B + (size_t)(n0 + lm) * 128 + k0 + lq * 4);
            Bs[(lq * 4 + 0) * 64 + lm] = bv.x;
            Bs[(lq * 4 + 1) * 64 + lm] = bv.y;
            Bs[(lq * 4 + 2) * 64 + lm] = bv.z;
            Bs[(lq * 4 + 3) * 64 + lm] = bv.w;
            __syncthreads();

#pragma unroll
            for (int k = 0; k < 16; k++) {
                float4 a = *(const float4*)&As[k * 64 + ty * 4];
                float4 b = *(const float4*)&Bs[k * 64 + tx * 4];
                acc[0][0] += a.x * b.x; acc[0][1] += a.x * b.y; acc[0][2] += a.x * b.z; acc[0][3] += a.x * b.w;
                acc[1][0] += a.y * b.x; acc[1][1] += a.y * b.y; acc[1][2] += a.y * b.z; acc[1][3] += a.y * b.w;
                acc[2][0] += a.z * b.x; acc[2][1] += a.z * b.y; acc[2][2] += a.z * b.z; acc[2][3] += a.z * b.w;
                acc[3][0] += a.w * b.x; acc[3][1] += a.w * b.y; acc[3][2] += a.w * b.z; acc[3][3] += a.w * b.w;
            }
            __syncthreads();
        }

#pragma unroll
        for (int i = 0; i < 4; i++) {
            int m = m0 + ty * 4 + i;
            if (m < Mc) {
#pragma unroll
                for (int j = 0; j < 4; j++) {
                    int n = n0 + tx * 4 + j;
                    C[(size_t)m * 512 + n] = acc[i][j] + bi1[n] + bi2[n];
                }
            }
        }
    }
}

// ---------------- sequential LSTM layer (device function; 512 threads) ----------------
// Thread tid owns gate row tid of whh[512,128]: 112 weights in regs (28 ull2),
// 16 via smem (4 ull2). Packed f32x2 reduction; branchless gx prefetch.
__device__ void lstm_seq(const float* __restrict__ gx, const float* __restrict__ whh,
                         float* __restrict__ hs,
                         float* __restrict__ outH, float* __restrict__ outC, int T,
                         int* prog, int* rdy, char* smem)
{
    float* h_sh = (float*)smem;                       // 128 floats
    float* g_sh = (float*)(smem + 512);               // 512 floats
    ulonglong2* wsm = (ulonglong2*)(smem + 2560);     // [4][512]

    int tid = threadIdx.x;
    const ulonglong2* wr = reinterpret_cast<const ulonglong2*>(whh + (size_t)tid * 128);
    ulonglong2 w[28];
#pragma unroll
    for (int q = 0; q < 28; q++) w[q] = wr[q];
#pragma unroll
    for (int q = 0; q < 4; q++) wsm[q * 512 + tid] = wr[28 + q];

    if (tid < 128) h_sh[tid] = 0.0f;
    float c = 0.0f;
    __syncthreads();

    const ulonglong2* h2 = reinterpret_cast<const ulonglong2*>(h_sh);
    const float* gxr = gx + tid;
    int nch = (T + CS - 1) / CS;

    for (int ci = 0; ci < nch; ci++) {
        int t0 = ci * CS, t1 = min(T, t0 + CS);
        if (rdy) {
            if (tid == 0) { while (ld_acq(&rdy[ci]) == 0) __nanosleep(64); }
            __syncthreads();
        }
        float gxv = __ldg(gxr + (size_t)t0 * 512);

        for (int t = t0; t < t1; t++) {
            int tn = (t + 1 < t1) ? (t + 1) : t;      // branchless clamp (stays in chunk)
            float gxn = __ldg(gxr + (size_t)tn * 512);

            ull a0 = 0ULL, a1 = 0ULL, a2 = 0ULL, a3 = 0ULL;
#pragma unroll
            for (int q = 0; q < 28; q++) {
                ulonglong2 hv = h2[q];
                if (q & 1) { a2 = ffma2(w[q].x, hv.x, a2); a3 = ffma2(w[q].y, hv.y, a3); }
                else       { a0 = ffma2(w[q].x, hv.x, a0); a1 = ffma2(w[q].y, hv.y, a1); }
            }
#pragma unroll
            for (int q = 0; q < 4; q++) {
                ulonglong2 hv = h2[28 + q];
                ulonglong2 wv = wsm[q * 512 + tid];
                if (q & 1) { a2 = ffma2(wv.x, hv.x, a2); a3 = ffma2(wv.y, hv.y, a3); }
                else       { a0 = ffma2(wv.x, hv.x, a0); a1 = ffma2(wv.y, hv.y, a1); }
            }
            a0 = addp(a0, a2);
            a1 = addp(a1, a3);
            a0 = addp(a0, a1);
            float2 f0 = upk(a0);
            float g = gxv + (f0.x + f0.y);
            g_sh[tid] = g;
            gxv = gxn;
            __syncthreads();               // all dots done; h_sh may now be overwritten

            if (tid < 128) {
                float ig = g_sh[tid];
                float fg = g_sh[tid + 128];
                float gg = g_sh[tid + 256];
                float og = g_sh[tid + 384];
                c = fast_sig(fg) * c + fast_sig(ig) * fast_tanh(gg);
                float h = fast_sig(og) * fast_tanh(c);
                h_sh[tid] = h;
                hs[(size_t)t * 128 + tid] = h;
            }
            __syncthreads();               // new h visible to all
        }

        if (prog && tid == 0) { __threadfence(); st_rel(prog, t1); }
    }

    if (tid < 128) { outH[tid] = h_sh[tid]; outC[tid] = c; }
}

// ---------------- pipelined LSTM kernel ----------------
// CTA0=layer0 (waits rdy0), CTA1=layer1 (waits rdy1),
// CTA2=gx0 producer (free-running), CTA3=gx1 producer (paced by prog0).
__global__ void __launch_bounds__(512, 1) k_pipe(
    const float* __restrict__ whh0, const float* __restrict__ whh1,
    const float* __restrict__ wih0,
    const float* __restrict__ bih0, const float* __restrict__ bhh0,
    const float* __restrict__ wih1,
    const float* __restrict__ bih1, const float* __restrict__ bhh1,
    float* outH, float* outC, int T)
{
    extern __shared__ char smem[];
    float* p_h   = g_h;
    float* p_hs0 = g_hs0;
    float* p_hs1 = g_hs1;
    float* p_gx0 = g_gx;
    float* p_gx1 = g_gx1;
    int role = blockIdx.x;
    int nch = (T + CS - 1) / CS;

    if (role == 0) {
        lstm_seq(p_gx0, whh0, p_hs0, outH, outC, T, &g_prog0, g_rdy0, smem);
    } else if (role == 1) {
        lstm_seq(p_gx1, whh1, p_hs1, outH + 128, outC + 128, T, nullptr, g_rdy, smem);
    } else if (role == 2) {
        // gx0 producer: inputs (p_h) ready at launch; runs ahead of layer0 freely
        for (int ci = 0; ci < nch; ci++) {
            int t0 = ci * CS, t1 = min(T, t0 + CS);
            gemm_chunk(p_h + (size_t)t0 * 128, t1 - t0, wih0, bih0, bhh0,
                       p_gx0 + (size_t)t0 * 512, (float*)smem);
            __syncthreads();
            if (threadIdx.x == 0) { __threadfence(); st_rel(&g_rdy0[ci], 1); }
            __syncthreads();
        }
    } else {
        // gx1 producer: paced by layer0 progress
        for (int ci = 0; ci < nch; ci++) {
            int t0 = ci * CS, t1 = min(T, t0 + CS);
            if (threadIdx.x == 0) { while (ld_acq(&g_prog0) < t1) __nanosleep(64); }
            __syncthreads();
            gemm_chunk(p_hs0 + (size_t)t0 * 128, t1 - t0, wih1, bih1, bhh1,
                       p_gx1 + (size_t)t0 * 512, (float*)smem);
            __syncthreads();
            if (threadIdx.x == 0) { __threadfence(); st_rel(&g_rdy[ci], 1); }
            __syncthreads();
        }
    }
}

// ---------------- edge head ----------------
__global__ void __launch_bounds__(256) k_edge(
    const float* __restrict__ hs1, const float* __restrict__ ef,
    const float* __restrict__ eW, const float* __restrict__ eb,
    const float* __restrict__ cW, const float* __restrict__ cb,
    float* __restrict__ pred, float* __restrict__ osrc, float* __restrict__ odst, int E)
{
    __shared__ __align__(16) float sW[32 * 128];
    __shared__ __align__(16) float scW[384];
    __shared__ __align__(16) float seb[128];
    int tid = threadIdx.x;
    for (int i = tid; i < 32 * 128; i += 256) sW[i] = eW[i];
    for (int i = tid; i < 384; i += 256) scW[i] = cW[i];
    if (tid < 128) seb[tid] = eb[tid];
    __syncthreads();

    int warp = tid >> 5, lane = tid & 31;
    int e = blockIdx.x * 8 + warp;
    if (e >= E) return;

    int s = g_src[e], d = g_dst[e];
    float4 sv = *(const float4*)(hs1 + (size_t)s * 128 + lane * 4);
    float4 dv = *(const float4*)(hs1 + (size_t)d * 128 + lane * 4);
    float efv = ef[(size_t)e * 32 + lane];

    float4 emb = *(const float4*)(seb + lane * 4);
#pragma unroll
    for (int k = 0; k < 32; k++) {
        float fk = __shfl_sync(0xffffffffu, efv, k);
        float4 wv = *(const float4*)(sW + k * 128 + lane * 4);
        emb.x += fk * wv.x; emb.y += fk * wv.y; emb.z += fk * wv.z; emb.w += fk * wv.w;
    }

    float4 c0 = *(const float4*)(scW + lane * 4);
    float4 c1 = *(const float4*)(scW + 128 + lane * 4);
    float4 c2 = *(const float4*)(scW + 256 + lane * 4);
    float p = sv.x * c0.x + sv.y * c0.y + sv.z * c0.z + sv.w * c0.w
            + dv.x * c1.x + dv.y * c1.y + dv.z * c1.z + dv.w * c1.w
            + emb.x * c2.x + emb.y * c2.y + emb.z * c2.z + emb.w * c2.w;
#pragma unroll
    for (int off = 16; off; off >>= 1) p += __shfl_xor_sync(0xffffffffu, p, off);
    if (lane == 0) pred[e] = p + cb[0];

    *(float4*)(osrc + (size_t)e * 128 + lane * 4) = sv;
    *(float4*)(odst + (size_t)e * 128 + lane * 4) = dv;
}

// ---------------- launch ----------------
extern "C" void kernel_launch(void* const* d_in, const int* in_sizes, int n_in,
                              void* d_out, int out_size)
{
    const float* x    = (const float*)d_in[0];
    const void*  ei   = d_in[1];
    const float* ef   = (const float*)d_in[2];
    const float* W1   = (const float*)d_in[3];
    const float* b1   = (const float*)d_in[4];
    const float* W2   = (const float*)d_in[5];
    const float* b2   = (const float*)d_in[6];
    const float* wih0 = (const float*)d_in[7];
    const float* whh0 = (const float*)d_in[8];
    const float* bih0 = (const float*)d_in[9];
    const float* bhh0 = (const float*)d_in[10];
    const float* wih1 = (const float*)d_in[11];
    const float* whh1 = (const float*)d_in[12];
    const float* bih1 = (const float*)d_in[13];
    const float* bhh1 = (const float*)d_in[14];
    const float* eW   = (const float*)d_in[15];
    const float* eb   = (const float*)d_in[16];
    const float* cW   = (const float*)d_in[17];
    const float* cb   = (const float*)d_in[18];

    int N = in_sizes[0] / 128;
    int E = in_sizes[1] / 2;
    float* out = (float*)d_out;

    float *p_xw, *p_h, *p_hs1;
    cudaGetSymbolAddress((void**)&p_xw,  g_xw);
    cudaGetSymbolAddress((void**)&p_h,   g_h);
    cudaGetSymbolAddress((void**)&p_hs1, g_hs1);

    static int smem_set = 0;
    if (!smem_set) {
        cudaFuncSetAttribute(k_pipe, cudaFuncAttributeMaxDynamicSharedMemorySize, 36864);
        smem_set = 1;
    }

    // edge index normalize + counter resets
    k_detect<<<1, 32>>>((const int*)ei);
    k_convert<<<(E + 255) / 256, 256>>>(ei, E, N);

    k_init<<<(N * 128 + 255) / 256, 256>>>(N);
    k_deg<<<(E + 255) / 256, 256>>>(E);
    k_rsqrt<<<(N + 255) / 256, 256>>>(N);

    dim3 g128(128 / 64, (N + 63) / 64);

    // GCN conv 1
    k_gemm<0><<<g128, 256>>>(x, W1, nullptr, nullptr, p_xw, N, 128);
    k_scatter<<<((size_t)E * 32 + 255) / 256, 256>>>(p_xw, E);
    k_finish<<<(N * 128 + 255) / 256, 256>>>(p_xw, b1, p_h, N, 1);

    // GCN conv 2
    k_gemm<0><<<g128, 256>>>(p_h, W2, nullptr, nullptr, p_xw, N, 128);
    k_scatter<<<((size_t)E * 32 + 255) / 256, 256>>>(p_xw, E);
    k_finish<<<(N * 128 + 255) / 256, 256>>>(p_xw, b2, p_h, N, 0);

    // output layout: pred[E] | hn[2*128] | cn[2*128] | src[E*128] | dst[E*128]
    float* out_hn  = out + E;
    float* out_cn  = out + E + 256;
    float* out_src = out + E + 512;
    float* out_dst = out_src + (size_t)E * 128;

    // fully pipelined LSTM: both gx GEMMs produced chunk-wise inside k_pipe
    k_pipe<<<4, 512, 36864>>>(whh0, whh1, wih0, bih0, bhh0,
                              wih1, bih1, bhh1, out_hn, out_cn, N);

    // edge head
    k_edge<<<(E + 7) / 8, 256>>>(p_hs1, ef, eW, eb, cW, cb, out, out_src, out_dst, E);
}

// round 16
// speedup vs baseline: 1.0239x; 1.0239x over previous
#include <cuda_runtime.h>
#include <cstdint>

#define NMAX 20000
#define EMAX 320000
#define CS   128           // LSTM pipeline chunk (steps)
#define NCHMAX ((NMAX + CS - 1) / CS)

typedef unsigned long long ull;

// ---------------- scratch (static device arrays; no allocation) ----------------
__device__ float g_dinv[NMAX];
__device__ float g_xw  [NMAX * 128];
__device__ float g_agg [NMAX * 128];
__device__ float g_h   [NMAX * 128];
__device__ float g_hs0 [NMAX * 128];
__device__ float g_hs1 [NMAX * 128];
__device__ float g_gx  [NMAX * 512];   // layer0 gate inputs (precomputed GEMM)
__device__ float g_gx1 [NMAX * 512];   // layer1 gate inputs (worker CTAs)
__device__ int   g_src [EMAX];
__device__ int   g_dst [EMAX];
__device__ int   g_flag[1];
__device__ int   g_prog0;              // layer0 published step count
__device__ int   g_rdy[NCHMAX];        // per-chunk gx1 ready flags

// ---------------- helpers ----------------
__device__ __forceinline__ ull ffma2(ull a, ull b, ull c) {
    ull d;
    asm("fma.rn.f32x2 %0, %1, %2, %3;" : "=l"(d) : "l"(a), "l"(b), "l"(c));
    return d;
}
__device__ __forceinline__ float2 upk(ull a) {
    float2 r;
    asm("mov.b64 {%0, %1}, %2;" : "=f"(r.x), "=f"(r.y) : "l"(a));
    return r;
}
__device__ __forceinline__ float fast_sig(float x) {
    float e; asm("ex2.approx.f32 %0, %1;" : "=f"(e) : "f"(-1.4426950408889634f * x));
    float r; asm("rcp.approx.f32 %0, %1;" : "=f"(r) : "f"(1.0f + e));
    return r;
}
__device__ __forceinline__ float fast_tanh(float x) {
    float e; asm("ex2.approx.f32 %0, %1;" : "=f"(e) : "f"(-2.8853900817779268f * x));
    float r; asm("rcp.approx.f32 %0, %1;" : "=f"(r) : "f"(1.0f + e));
    return fmaf(2.0f, r, -1.0f);
}
__device__ __forceinline__ int ld_acq(const int* p) {
    int v; asm volatile("ld.acquire.gpu.b32 %0, [%1];" : "=r"(v) : "l"(p)); return v;
}
__device__ __forceinline__ void st_rel(int* p, int v) {
    asm volatile("st.release.gpu.b32 [%0], %1;" :: "l"(p), "r"(v));
}

// ---------------- edge index dtype detect + normalize ----------------
__global__ void k_detect(const int* ei) {
    if (threadIdx.x == 0 && blockIdx.x == 0) {
        int nz = 0;
        for (int i = 0; i < 128; i++) nz += (ei[2 * i + 1] != 0);
        g_flag[0] = (nz == 0) ? 1 : 0;
    }
}

__global__ void k_convert(const void* ei, int E, int N) {
    int e = blockIdx.x * blockDim.x + threadIdx.x;
    if (e >= E) return;
    int s, d;
    if (g_flag[0]) {
        const long long* p = (const long long*)ei;
        s = (int)p[e]; d = (int)p[E + e];
    } else {
        const int* p = (const int*)ei;
        s = p[e]; d = p[E + e];
    }
    s = min(max(s, 0), N - 1);
    d = min(max(d, 0), N - 1);
    g_src[e] = s; g_dst[e] = d;
}

// ---------------- GCN: init (+ pipeline counter reset) ----------------
__global__ void k_init(int N) {
    int i = blockIdx.x * blockDim.x + threadIdx.x;
    if (i < N * 128) g_agg[i] = 0.0f;
    if (i < N)       g_dinv[i] = 1.0f;
    if (i == 0)      g_prog0 = 0;
    if (i < NCHMAX)  g_rdy[i] = 0;
}

__global__ void k_deg(int E) {
    int e = blockIdx.x * blockDim.x + threadIdx.x;
    if (e < E) atomicAdd(&g_dinv[g_dst[e]], 1.0f);
}

__global__ void k_rsqrt(int N) {
    int i = blockIdx.x * blockDim.x + threadIdx.x;
    if (i < N) g_dinv[i] = rsqrtf(g_dinv[i]);
}

// ---------------- generic K=128 GEMM ----------------
template <int TRANSB>
__global__ void __launch_bounds__(256) k_gemm(
    const float* __restrict__ A, const float* __restrict__ B,
    const float* __restrict__ bias1, const float* __restrict__ bias2,
    float* __restrict__ C, int M, int NC)
{
    __shared__ __align__(16) float As[16][64];
    __shared__ __align__(16) float Bs[16][64];
    int tid = threadIdx.x;
    int m0 = blockIdx.y * 64, n0 = blockIdx.x * 64;
    int tx = tid & 15, ty = tid >> 4;
    float acc[4][4];
#pragma unroll
    for (int i = 0; i < 4; i++)
#pragma unroll
        for (int j = 0; j < 4; j++) acc[i][j] = 0.0f;

    int lm = tid >> 2, lq = tid & 3;

    for (int k0 = 0; k0 < 128; k0 += 16) {
        float4 av = make_float4(0.f, 0.f, 0.f, 0.f);
        if (m0 + lm < M)
            av = *(const float4*)(A + (size_t)(m0 + lm) * 128 + k0 + lq * 4);
        As[lq * 4 + 0][lm] = av.x;
        As[lq * 4 + 1][lm] = av.y;
        As[lq * 4 + 2][lm] = av.z;
        As[lq * 4 + 3][lm] = av.w;

        if (TRANSB) {
            float4 bv = *(const float4*)(B + (size_t)(n0 + lm) * 128 + k0 + lq * 4);
            Bs[lq * 4 + 0][lm] = bv.x;
            Bs[lq * 4 + 1][lm] = bv.y;
            Bs[lq * 4 + 2][lm] = bv.z;
            Bs[lq * 4 + 3][lm] = bv.w;
        } else {
            int bk = tid >> 4, bn = tid & 15;
            float4 bv = *(const float4*)(B + (size_t)(k0 + bk) * NC + n0 + bn * 4);
            *(float4*)&Bs[bk][bn * 4] = bv;
        }
        __syncthreads();

#pragma unroll
        for (int k = 0; k < 16; k++) {
            float4 a = *(const float4*)&As[k][ty * 4];
            float4 b = *(const float4*)&Bs[k][tx * 4];
            acc[0][0] += a.x * b.x; acc[0][1] += a.x * b.y; acc[0][2] += a.x * b.z; acc[0][3] += a.x * b.w;
            acc[1][0] += a.y * b.x; acc[1][1] += a.y * b.y; acc[1][2] += a.y * b.z; acc[1][3] += a.y * b.w;
            acc[2][0] += a.z * b.x; acc[2][1] += a.z * b.y; acc[2][2] += a.z * b.z; acc[2][3] += a.z * b.w;
            acc[3][0] += a.w * b.x; acc[3][1] += a.w * b.y; acc[3][2] += a.w * b.z; acc[3][3] += a.w * b.w;
        }
        __syncthreads();
    }

    float bb[4] = {0.f, 0.f, 0.f, 0.f};
    if (bias1) {
#pragma unroll
        for (int j = 0; j < 4; j++) bb[j] += bias1[n0 + tx * 4 + j];
    }
    if (bias2) {
#pragma unroll
        for (int j = 0; j < 4; j++) bb[j] += bias2[n0 + tx * 4 + j];
    }
#pragma unroll
    for (int i = 0; i < 4; i++) {
        int m = m0 + ty * 4 + i;
        if (m < M) {
#pragma unroll
            for (int j = 0; j < 4; j++)
                C[(size_t)m * NC + n0 + tx * 4 + j] = acc[i][j] + bb[j];
        }
    }
}

// ---------------- GCN scatter (atomic aggregate) ----------------
__global__ void k_scatter(const float* __restrict__ xw, int E) {
    int idx = blockIdx.x * blockDim.x + threadIdx.x;
    int e = idx >> 5, lane = idx & 31;
    if (e >= E) return;
    int s = g_src[e], d = g_dst[e];
    float nrm = g_dinv[s] * g_dinv[d];
    float4 v = *(const float4*)(xw + (size_t)s * 128 + lane * 4);
    float* out = g_agg + (size_t)d * 128 + lane * 4;
    atomicAdd(out + 0, v.x * nrm);
    atomicAdd(out + 1, v.y * nrm);
    atomicAdd(out + 2, v.z * nrm);
    atomicAdd(out + 3, v.w * nrm);
}

__global__ void k_finish(const float* __restrict__ xw, const float* __restrict__ bias,
                         float* __restrict__ out, int N, int relu) {
    int idx = blockIdx.x * blockDim.x + threadIdx.x;
    if (idx >= N * 128) return;
    int i = idx >> 7, c = idx & 127;
    float di = g_dinv[i];
    float v = g_agg[idx] + xw[idx] * di * di + bias[c];
    if (relu) v = fmaxf(v, 0.0f);
    out[idx] = v;
    g_agg[idx] = 0.0f;
}

// ---------------- worker GEMM for one chunk: C[Mc,512] = A[Mc,128] @ B[512,128]^T + b ---
// 512 threads = 2 groups of 256; both groups iterate identical tile counts (barrier-safe).
__device__ void gemm_chunk(const float* __restrict__ A, int Mc,
                           const float* __restrict__ B,
                           const float* __restrict__ bi1, const float* __restrict__ bi2,
                           float* __restrict__ C, float* smem)
{
    int tid = threadIdx.x;
    int grp = tid >> 8, gt = tid & 255;
    float* As = smem + grp * 2048;     // [16][64]
    float* Bs = As + 1024;             // [16][64]
    int tx = gt & 15, ty = gt >> 4;
    int lm = gt >> 2, lq = gt & 3;
    int mt = (Mc + 63) >> 6;
    int nTiles = mt * 8;               // always even (8 or 16)

    for (int p = 0; p < nTiles; p += 2) {
        int idx = p + grp;
        int m0 = (idx >> 3) << 6, n0 = (idx & 7) << 6;
        float acc[4][4];
#pragma unroll
        for (int i = 0; i < 4; i++)
#pragma unroll
            for (int j = 0; j < 4; j++) acc[i][j] = 0.0f;

        for (int k0 = 0; k0 < 128; k0 += 16) {
            float4 av = make_float4(0.f, 0.f, 0.f, 0.f);
            if (m0 + lm < Mc)
                av = *(const float4*)(A + (size_t)(m0 + lm) * 128 + k0 + lq * 4);
            As[(lq * 4 + 0) * 64 + lm] = av.x;
            As[(lq * 4 + 1) * 64 + lm] = av.y;
            As[(lq * 4 + 2) * 64 + lm] = av.z;
            As[(lq * 4 + 3) * 64 + lm] = av.w;

            float4 bv = *(const float4*)(B + (size_t)(n0 + lm) * 128 + k0 + lq * 4);
            Bs[(lq * 4 + 0) * 64 + lm] = bv.x;
            Bs[(lq * 4 + 1) * 64 + lm] = bv.y;
            Bs[(lq * 4 + 2) * 64 + lm] = bv.z;
            Bs[(lq * 4 + 3) * 64 + lm] = bv.w;
            __syncthreads();

#pragma unroll
            for (int k = 0; k < 16; k++) {
                float4 a = *(const float4*)&As[k * 64 + ty * 4];
                float4 b = *(const float4*)&Bs[k * 64 + tx * 4];
                acc[0][0] += a.x * b.x; acc[0][1] += a.x * b.y; acc[0][2] += a.x * b.z; acc[0][3] += a.x * b.w;
                acc[1][0] += a.y * b.x; acc[1][1] += a.y * b.y; acc[1][2] += a.y * b.z; acc[1][3] += a.y * b.w;
                acc[2][0] += a.z * b.x; acc[2][1] += a.z * b.y; acc[2][2] += a.z * b.z; acc[2][3] += a.z * b.w;
                acc[3][0] += a.w * b.x; acc[3][1] += a.w * b.y; acc[3][2] += a.w * b.z; acc[3][3] += a.w * b.w;
            }
            __syncthreads();
        }

#pragma unroll
        for (int i = 0; i < 4; i++) {
            int m = m0 + ty * 4 + i;
            if (m < Mc) {
#pragma unroll
                for (int j = 0; j < 4; j++) {
                    int n = n0 + tx * 4 + j;
                    C[(size_t)m * 512 + n] = acc[i][j] + bi1[n] + bi2[n];
                }
            }
        }
    }
}

// ---------------- sequential LSTM layer (device function; 512 threads) ----------------
// Thread tid owns gate row tid of whh[512,128]: 112 weights in regs (28 ull2),
// 16 via smem (4 ull2). NEW: per-gate activation applied by the OWNING thread
// before barrier #1 (warp-uniform branch; 4 whole warps per gate block), so the
// tail's serial MUFU chain shrinks to a single tanh.
__device__ void lstm_seq(const float* __restrict__ gx, const float* __restrict__ whh,
                         float* __restrict__ hs,
                         float* __restrict__ outH, float* __restrict__ outC, int T,
                         int* prog, int* rdy, char* smem)
{
    float* h_sh = (float*)smem;                       // 128 floats
    float* g_sh = (float*)(smem + 512);               // 512 floats
    ulonglong2* wsm = (ulonglong2*)(smem + 2560);     // [4][512]

    int tid = threadIdx.x;
    const ulonglong2* wr = reinterpret_cast<const ulonglong2*>(whh + (size_t)tid * 128);
    ulonglong2 w[28];
#pragma unroll
    for (int q = 0; q < 28; q++) w[q] = wr[q];
#pragma unroll
    for (int q = 0; q < 4; q++) wsm[q * 512 + tid] = wr[28 + q];

    if (tid < 128) h_sh[tid] = 0.0f;
    float c = 0.0f;
    __syncthreads();

    const ulonglong2* h2 = reinterpret_cast<const ulonglong2*>(h_sh);
    int isTanhRow = ((tid & 384) == 256);             // rows 256..383 = g gate
    int nch = (T + CS - 1) / CS;

    for (int ci = 0; ci < nch; ci++) {
        int t0 = ci * CS, t1 = min(T, t0 + CS);
        if (rdy) {
            if (tid == 0) { while (ld_acq(&rdy[ci]) == 0) __nanosleep(64); }
            __syncthreads();
        }
        float gxv = __ldg(gx + (size_t)t0 * 512 + tid);

        for (int t = t0; t < t1; t++) {
            float gxn = 0.0f;
            if (t + 1 < t1) gxn = __ldg(gx + (size_t)(t + 1) * 512 + tid);

            ull a0 = 0ULL, a1 = 0ULL, a2 = 0ULL, a3 = 0ULL;
#pragma unroll
            for (int q = 0; q < 28; q++) {
                ulonglong2 hv = h2[q];
                if (q & 1) { a2 = ffma2(w[q].x, hv.x, a2); a3 = ffma2(w[q].y, hv.y, a3); }
                else       { a0 = ffma2(w[q].x, hv.x, a0); a1 = ffma2(w[q].y, hv.y, a1); }
            }
#pragma unroll
            for (int q = 0; q < 4; q++) {
                ulonglong2 hv = h2[28 + q];
                ulonglong2 wv = wsm[q * 512 + tid];
                if (q & 1) { a2 = ffma2(wv.x, hv.x, a2); a3 = ffma2(wv.y, hv.y, a3); }
                else       { a0 = ffma2(wv.x, hv.x, a0); a1 = ffma2(wv.y, hv.y, a1); }
            }
            float2 f0 = upk(a0), f1 = upk(a1), f2 = upk(a2), f3 = upk(a3);
            float g = gxv + (((f0.x + f0.y) + (f1.x + f1.y)) + ((f2.x + f2.y) + (f3.x + f3.y)));
            // pre-activate in the owning thread (warp-uniform branch)
            if (isTanhRow) g = fast_tanh(g);
            else           g = fast_sig(g);
            g_sh[tid] = g;
            gxv = gxn;
            __syncthreads();               // all activated gates visible

            if (tid < 128) {
                float ig = g_sh[tid];          // sig(i) already applied
                float fg = g_sh[tid + 128];    // sig(f)
                float gg = g_sh[tid + 256];    // tanh(g)
                float og = g_sh[tid + 384];    // sig(o)
                c = fg * c + ig * gg;
                float h = og * fast_tanh(c);
                h_sh[tid] = h;
                hs[(size_t)t * 128 + tid] = h;
            }
            __syncthreads();               // new h visible to all
        }

        if (prog && tid == 0) { __threadfence(); st_rel(prog, t1); }
    }

    if (tid < 128) { outH[tid] = h_sh[tid]; outC[tid] = c; }
}

// ---------------- pipelined LSTM kernel: CTA0=layer0, CTA1=layer1, CTA2-3=gx1 workers ---
__global__ void __launch_bounds__(512, 1) k_pipe(
    const float* __restrict__ gx0,
    const float* __restrict__ whh0, const float* __restrict__ whh1,
    const float* __restrict__ wih1,
    const float* __restrict__ bih1, const float* __restrict__ bhh1,
    float* outH, float* outC, int T)
{
    extern __shared__ char smem[];
    float* p_hs0 = g_hs0;
    float* p_hs1 = g_hs1;
    float* p_gx1 = g_gx1;
    int role = blockIdx.x;

    if (role == 0) {
        lstm_seq(gx0, whh0, p_hs0, outH, outC, T, &g_prog0, nullptr, smem);
    } else if (role == 1) {
        lstm_seq(p_gx1, whh1, p_hs1, outH + 128, outC + 128, T, nullptr, g_rdy, smem);
    } else {
        int widx = role - 2;
        int nch = (T + CS - 1) / CS;
        for (int ci = widx; ci < nch; ci += 2) {
            int t0 = ci * CS, t1 = min(T, t0 + CS);
            if (threadIdx.x == 0) { while (ld_acq(&g_prog0) < t1) __nanosleep(64); }
            __syncthreads();
            gemm_chunk(p_hs0 + (size_t)t0 * 128, t1 - t0, wih1, bih1, bhh1,
                       p_gx1 + (size_t)t0 * 512, (float*)smem);
            __syncthreads();
            if (threadIdx.x == 0) { __threadfence(); st_rel(&g_rdy[ci], 1); }
        }
    }
}

// ---------------- edge head ----------------
__global__ void __launch_bounds__(256) k_edge(
    const float* __restrict__ hs1, const float* __restrict__ ef,
    const float* __restrict__ eW, const float* __restrict__ eb,
    const float* __restrict__ cW, const float* __restrict__ cb,
    float* __restrict__ pred, float* __restrict__ osrc, float* __restrict__ odst, int E)
{
    __shared__ __align__(16) float sW[32 * 128];
    __shared__ __align__(16) float scW[384];
    __shared__ __align__(16) float seb[128];
    int tid = threadIdx.x;
    for (int i = tid; i < 32 * 128; i += 256) sW[i] = eW[i];
    for (int i = tid; i < 384; i += 256) scW[i] = cW[i];
    if (tid < 128) seb[tid] = eb[tid];
    __syncthreads();

    int warp = tid >> 5, lane = tid & 31;
    int e = blockIdx.x * 8 + warp;
    if (e >= E) return;

    int s = g_src[e], d = g_dst[e];
    float4 sv = *(const float4*)(hs1 + (size_t)s * 128 + lane * 4);
    float4 dv = *(const float4*)(hs1 + (size_t)d * 128 + lane * 4);
    float efv = ef[(size_t)e * 32 + lane];

    float4 emb = *(const float4*)(seb + lane * 4);
#pragma unroll
    for (int k = 0; k < 32; k++) {
        float fk = __shfl_sync(0xffffffffu, efv, k);
        float4 wv = *(const float4*)(sW + k * 128 + lane * 4);
        emb.x += fk * wv.x; emb.y += fk * wv.y; emb.z += fk * wv.z; emb.w += fk * wv.w;
    }

    float4 c0 = *(const float4*)(scW + lane * 4);
    float4 c1 = *(const float4*)(scW + 128 + lane * 4);
    float4 c2 = *(const float4*)(scW + 256 + lane * 4);
    float p = sv.x * c0.x + sv.y * c0.y + sv.z * c0.z + sv.w * c0.w
            + dv.x * c1.x + dv.y * c1.y + dv.z * c1.z + dv.w * c1.w
            + emb.x * c2.x + emb.y * c2.y + emb.z * c2.z + emb.w * c2.w;
#pragma unroll
    for (int off = 16; off; off >>= 1) p += __shfl_xor_sync(0xffffffffu, p, off);
    if (lane == 0) pred[e] = p + cb[0];

    *(float4*)(osrc + (size_t)e * 128 + lane * 4) = sv;
    *(float4*)(odst + (size_t)e * 128 + lane * 4) = dv;
}

// ---------------- launch ----------------
extern "C" void kernel_launch(void* const* d_in, const int* in_sizes, int n_in,
                              void* d_out, int out_size)
{
    const float* x    = (const float*)d_in[0];
    const void*  ei   = d_in[1];
    const float* ef   = (const float*)d_in[2];
    const float* W1   = (const float*)d_in[3];
    const float* b1   = (const float*)d_in[4];
    const float* W2   = (const float*)d_in[5];
    const float* b2   = (const float*)d_in[6];
    const float* wih0 = (const float*)d_in[7];
    const float* whh0 = (const float*)d_in[8];
    const float* bih0 = (const float*)d_in[9];
    const float* bhh0 = (const float*)d_in[10];
    const float* wih1 = (const float*)d_in[11];
    const float* whh1 = (const float*)d_in[12];
    const float* bih1 = (const float*)d_in[13];
    const float* bhh1 = (const float*)d_in[14];
    const float* eW   = (const float*)d_in[15];
    const float* eb   = (const float*)d_in[16];
    const float* cW   = (const float*)d_in[17];
    const float* cb   = (const float*)d_in[18];

    int N = in_sizes[0] / 128;
    int E = in_sizes[1] / 2;
    float* out = (float*)d_out;

    float *p_xw, *p_h, *p_hs1, *p_gx;
    cudaGetSymbolAddress((void**)&p_xw,  g_xw);
    cudaGetSymbolAddress((void**)&p_h,   g_h);
    cudaGetSymbolAddress((void**)&p_hs1, g_hs1);
    cudaGetSymbolAddress((void**)&p_gx,  g_gx);

    static int smem_set = 0;
    if (!smem_set) {
        cudaFuncSetAttribute(k_pipe, cudaFuncAttributeMaxDynamicSharedMemorySize, 36864);
        smem_set = 1;
    }

    // edge index normalize + counter resets
    k_detect<<<1, 32>>>((const int*)ei);
    k_convert<<<(E + 255) / 256, 256>>>(ei, E, N);

    k_init<<<(N * 128 + 255) / 256, 256>>>(N);
    k_deg<<<(E + 255) / 256, 256>>>(E);
    k_rsqrt<<<(N + 255) / 256, 256>>>(N);

    dim3 g128(128 / 64, (N + 63) / 64);
    dim3 g512(512 / 64, (N + 63) / 64);

    // GCN conv 1
    k_gemm<0><<<g128, 256>>>(x, W1, nullptr, nullptr, p_xw, N, 128);
    k_scatter<<<((size_t)E * 32 + 255) / 256, 256>>>(p_xw, E);
    k_finish<<<(N * 128 + 255) / 256, 256>>>(p_xw, b1, p_h, N, 1);

    // GCN conv 2
    k_gemm<0><<<g128, 256>>>(p_h, W2, nullptr, nullptr, p_xw, N, 128);
    k_scatter<<<((size_t)E * 32 + 255) / 256, 256>>>(p_xw, E);
    k_finish<<<(N * 128 + 255) / 256, 256>>>(p_xw, b2, p_h, N, 0);

    // output layout: pred[E] | hn[2*128] | cn[2*128] | src[E*128] | dst[E*128]
    float* out_hn  = out + E;
    float* out_cn  = out + E + 256;
    float* out_src = out + E + 512;
    float* out_dst = out_src + (size_t)E * 128;

    // layer0 gate-input GEMM (full, parallel)
    k_gemm<1><<<g512, 256>>>(p_h, wih0, bih0, bhh0, p_gx, N, 512);

    // pipelined LSTM: layer0 + layer1 + 2 gx1-GEMM workers, one launch (grid=4)
    k_pipe<<<4, 512, 36864>>>(p_gx, whh0, whh1, wih1, bih1, bhh1, out_hn, out_cn, N);

    // edge head
    k_edge<<<(E + 7) / 8, 256>>>(p_hs1, ef, eW, eb, cW, cb, out, out_src, out_dst, E);
}

// round 17
// speedup vs baseline: 1.0739x; 1.0488x over previous
#include <cuda_runtime.h>
#include <cstdint>

#define NMAX 20000
#define EMAX 320000
#define CS   128           // LSTM pipeline chunk (steps)
#define NCHMAX ((NMAX + CS - 1) / CS)

typedef unsigned long long ull;

// ---------------- scratch (static device arrays; no allocation) ----------------
__device__ float g_dinv[NMAX];
__device__ float g_xw  [NMAX * 128];
__device__ float g_agg [NMAX * 128];
__device__ float g_h   [NMAX * 128];
__device__ float g_hs0 [NMAX * 128];
__device__ float g_hs1 [NMAX * 128];
__device__ float g_gx  [NMAX * 512];   // layer0 gate inputs (precomputed GEMM)
__device__ float g_gx1 [NMAX * 512];   // layer1 gate inputs (worker CTAs)
__device__ int   g_src [EMAX];
__device__ int   g_dst [EMAX];
__device__ int   g_flag[1];
__device__ int   g_prog0;              // layer0 published step count
__device__ int   g_rdy[NCHMAX];        // per-chunk gx1 ready flags

// ---------------- helpers ----------------
__device__ __forceinline__ ull ffma2(ull a, ull b, ull c) {
    ull d;
    asm("fma.rn.f32x2 %0, %1, %2, %3;" : "=l"(d) : "l"(a), "l"(b), "l"(c));
    return d;
}
__device__ __forceinline__ float2 upk(ull a) {
    float2 r;
    asm("mov.b64 {%0, %1}, %2;" : "=f"(r.x), "=f"(r.y) : "l"(a));
    return r;
}
__device__ __forceinline__ float fast_sig(float x) {
    float e; asm("ex2.approx.f32 %0, %1;" : "=f"(e) : "f"(-1.4426950408889634f * x));
    float r; asm("rcp.approx.f32 %0, %1;" : "=f"(r) : "f"(1.0f + e));
    return r;
}
__device__ __forceinline__ float fast_tanh(float x) {
    float e; asm("ex2.approx.f32 %0, %1;" : "=f"(e) : "f"(-2.8853900817779268f * x));
    float r; asm("rcp.approx.f32 %0, %1;" : "=f"(r) : "f"(1.0f + e));
    return fmaf(2.0f, r, -1.0f);
}
__device__ __forceinline__ int ld_acq(const int* p) {
    int v; asm volatile("ld.acquire.gpu.b32 %0, [%1];" : "=r"(v) : "l"(p)); return v;
}
__device__ __forceinline__ void st_rel(int* p, int v) {
    asm volatile("st.release.gpu.b32 [%0], %1;" :: "l"(p), "r"(v));
}
__device__ __forceinline__ void red_add_v4(float* p, float4 v) {
    asm volatile("red.global.add.v4.f32 [%0], {%1, %2, %3, %4};"
                 :: "l"(p), "f"(v.x), "f"(v.y), "f"(v.z), "f"(v.w) : "memory");
}

// ---------------- edge index dtype detect ----------------
__global__ void k_detect(const int* ei) {
    if (threadIdx.x == 0 && blockIdx.x == 0) {
        int nz = 0;
        for (int i = 0; i < 128; i++) nz += (ei[2 * i + 1] != 0);
        g_flag[0] = (nz == 0) ? 1 : 0;
    }
}

// ---------------- init (+ pipeline counter reset) ----------------
__global__ void k_init(int N) {
    int i = blockIdx.x * blockDim.x + threadIdx.x;
    if (i < N * 128) g_agg[i] = 0.0f;
    if (i < N)       g_dinv[i] = 1.0f;
    if (i == 0)      g_prog0 = 0;
    if (i < NCHMAX)  g_rdy[i] = 0;
}

// ---------------- convert + degree (fused) ----------------
__global__ void k_convert(const void* ei, int E, int N) {
    int e = blockIdx.x * blockDim.x + threadIdx.x;
    if (e >= E) return;
    int s, d;
    if (g_flag[0]) {
        const long long* p = (const long long*)ei;
        s = (int)p[e]; d = (int)p[E + e];
    } else {
        const int* p = (const int*)ei;
        s = p[e]; d = p[E + e];
    }
    s = min(max(s, 0), N - 1);
    d = min(max(d, 0), N - 1);
    g_src[e] = s; g_dst[e] = d;
    atomicAdd(&g_dinv[d], 1.0f);
}

__global__ void k_rsqrt(int N) {
    int i = blockIdx.x * blockDim.x + threadIdx.x;
    if (i < N) g_dinv[i] = rsqrtf(g_dinv[i]);
}

// ---------------- generic K=128 GEMM (optional per-row output scale) ----------------
template <int TRANSB>
__global__ void __launch_bounds__(256) k_gemm(
    const float* __restrict__ A, const float* __restrict__ B,
    const float* __restrict__ bias1, const float* __restrict__ bias2,
    const float* __restrict__ rowscale,
    float* __restrict__ C, int M, int NC)
{
    __shared__ __align__(16) float As[16][64];
    __shared__ __align__(16) float Bs[16][64];
    int tid = threadIdx.x;
    int m0 = blockIdx.y * 64, n0 = blockIdx.x * 64;
    int tx = tid & 15, ty = tid >> 4;
    float acc[4][4];
#pragma unroll
    for (int i = 0; i < 4; i++)
#pragma unroll
        for (int j = 0; j < 4; j++) acc[i][j] = 0.0f;

    int lm = tid >> 2, lq = tid & 3;

    for (int k0 = 0; k0 < 128; k0 += 16) {
        float4 av = make_float4(0.f, 0.f, 0.f, 0.f);
        if (m0 + lm < M)
            av = *(const float4*)(A + (size_t)(m0 + lm) * 128 + k0 + lq * 4);
        As[lq * 4 + 0][lm] = av.x;
        As[lq * 4 + 1][lm] = av.y;
        As[lq * 4 + 2][lm] = av.z;
        As[lq * 4 + 3][lm] = av.w;

        if (TRANSB) {
            float4 bv = *(const float4*)(B + (size_t)(n0 + lm) * 128 + k0 + lq * 4);
            Bs[lq * 4 + 0][lm] = bv.x;
            Bs[lq * 4 + 1][lm] = bv.y;
            Bs[lq * 4 + 2][lm] = bv.z;
            Bs[lq * 4 + 3][lm] = bv.w;
        } else {
            int bk = tid >> 4, bn = tid & 15;
            float4 bv = *(const float4*)(B + (size_t)(k0 + bk) * NC + n0 + bn * 4);
            *(float4*)&Bs[bk][bn * 4] = bv;
        }
        __syncthreads();

#pragma unroll
        for (int k = 0; k < 16; k++) {
            float4 a = *(const float4*)&As[k][ty * 4];
            float4 b = *(const float4*)&Bs[k][tx * 4];
            acc[0][0] += a.x * b.x; acc[0][1] += a.x * b.y; acc[0][2] += a.x * b.z; acc[0][3] += a.x * b.w;
            acc[1][0] += a.y * b.x; acc[1][1] += a.y * b.y; acc[1][2] += a.y * b.z; acc[1][3] += a.y * b.w;
            acc[2][0] += a.z * b.x; acc[2][1] += a.z * b.y; acc[2][2] += a.z * b.z; acc[2][3] += a.z * b.w;
            acc[3][0] += a.w * b.x; acc[3][1] += a.w * b.y; acc[3][2] += a.w * b.z; acc[3][3] += a.w * b.w;
        }
        __syncthreads();
    }

    float bb[4] = {0.f, 0.f, 0.f, 0.f};
    if (bias1) {
#pragma unroll
        for (int j = 0; j < 4; j++) bb[j] += bias1[n0 + tx * 4 + j];
    }
    if (bias2) {
#pragma unroll
        for (int j = 0; j < 4; j++) bb[j] += bias2[n0 + tx * 4 + j];
    }
#pragma unroll
    for (int i = 0; i < 4; i++) {
        int m = m0 + ty * 4 + i;
        if (m < M) {
            float sc = rowscale ? rowscale[m] : 1.0f;
#pragma unroll
            for (int j = 0; j < 4; j++)
                C[(size_t)m * NC + n0 + tx * 4 + j] = acc[i][j] * sc + bb[j];
        }
    }
}

// ---------------- GCN scatter: pure vector-red add of prescaled rows ----------------
__global__ void k_scatter(const float* __restrict__ y, int E) {
    int idx = blockIdx.x * blockDim.x + threadIdx.x;
    int e = idx >> 5, lane = idx & 31;
    if (e >= E) return;
    int s = g_src[e], d = g_dst[e];
    float4 v = *(const float4*)(y + (size_t)s * 128 + lane * 4);
    red_add_v4(g_agg + (size_t)d * 128 + lane * 4, v);
}

// out = (agg + y_i) * dinv_i + b  (self-loop folded; y is prescaled xw*dinv)
__global__ void k_finish(const float* __restrict__ y, const float* __restrict__ bias,
                         float* __restrict__ out, int N, int relu) {
    int idx = blockIdx.x * blockDim.x + threadIdx.x;
    if (idx >= N * 128) return;
    int i = idx >> 7, c = idx & 127;
    float di = g_dinv[i];
    float v = (g_agg[idx] + y[idx]) * di + bias[c];
    if (relu) v = fmaxf(v, 0.0f);
    out[idx] = v;
    g_agg[idx] = 0.0f;
}

// ---------------- worker GEMM for one chunk: C[Mc,512] = A[Mc,128] @ B[512,128]^T + b ---
// 512 threads = 2 groups of 256; both groups iterate identical tile counts (barrier-safe).
__device__ void gemm_chunk(const float* __restrict__ A, int Mc,
                           const float* __restrict__ B,
                           const float* __restrict__ bi1, const float* __restrict__ bi2,
                           float* __restrict__ C, float* smem)
{
    int tid = threadIdx.x;
    int grp = tid >> 8, gt = tid & 255;
    float* As = smem + grp * 2048;     // [16][64]
    float* Bs = As + 1024;             // [16][64]
    int tx = gt & 15, ty = gt >> 4;
    int lm = gt >> 2, lq = gt & 3;
    int mt = (Mc + 63) >> 6;
    int nTiles = mt * 8;               // always even (8 or 16)

    for (int p = 0; p < nTiles; p += 2) {
        int idx = p + grp;
        int m0 = (idx >> 3) << 6, n0 = (idx & 7) << 6;
        float acc[4][4];
#pragma unroll
        for (int i = 0; i < 4; i++)
#pragma unroll
            for (int j = 0; j < 4; j++) acc[i][j] = 0.0f;

        for (int k0 = 0; k0 < 128; k0 += 16) {
            float4 av = make_float4(0.f, 0.f, 0.f, 0.f);
            if (m0 + lm < Mc)
                av = *(const float4*)(A + (size_t)(m0 + lm) * 128 + k0 + lq * 4);
            As[(lq * 4 + 0) * 64 + lm] = av.x;
            As[(lq * 4 + 1) * 64 + lm] = av.y;
            As[(lq * 4 + 2) * 64 + lm] = av.z;
            As[(lq * 4 + 3) * 64 + lm] = av.w;

            float4 bv = *(const float4*)(B + (size_t)(n0 + lm) * 128 + k0 + lq * 4);
            Bs[(lq * 4 + 0) * 64 + lm] = bv.x;
            Bs[(lq * 4 + 1) * 64 + lm] = bv.y;
            Bs[(lq * 4 + 2) * 64 + lm] = bv.z;
            Bs[(lq * 4 + 3) * 64 + lm] = bv.w;
            __syncthreads();

#pragma unroll
            for (int k = 0; k < 16; k++) {
                float4 a = *(const float4*)&As[k * 64 + ty * 4];
                float4 b = *(const float4*)&Bs[k * 64 + tx * 4];
                acc[0][0] += a.x * b.x; acc[0][1] += a.x * b.y; acc[0][2] += a.x * b.z; acc[0][3] += a.x * b.w;
                acc[1][0] += a.y * b.x; acc[1][1] += a.y * b.y; acc[1][2] += a.y * b.z; acc[1][3] += a.y * b.w;
                acc[2][0] += a.z * b.x; acc[2][1] += a.z * b.y; acc[2][2] += a.z * b.z; acc[2][3] += a.z * b.w;
                acc[3][0] += a.w * b.x; acc[3][1] += a.w * b.y; acc[3][2] += a.w * b.z; acc[3][3] += a.w * b.w;
            }
            __syncthreads();
        }

#pragma unroll
        for (int i = 0; i < 4; i++) {
            int m = m0 + ty * 4 + i;
            if (m < Mc) {
#pragma unroll
                for (int j = 0; j < 4; j++) {
                    int n = n0 + tx * 4 + j;
                    C[(size_t)m * 512 + n] = acc[i][j] + bi1[n] + bi2[n];
                }
            }
        }
    }
}

// ---------------- sequential LSTM layer (device function; 512 threads) ----------------
// Exact R13-winning configuration: 112 weights in regs (28 ull2), 16 via smem,
// predicated gx prefetch, scalar reduction, consolidated serial tail, 2 barriers.
__device__ void lstm_seq(const float* __restrict__ gx, const float* __restrict__ whh,
                         float* __restrict__ hs,
                         float* __restrict__ outH, float* __restrict__ outC, int T,
                         int* prog, int* rdy, char* smem)
{
    float* h_sh = (float*)smem;                       // 128 floats
    float* g_sh = (float*)(smem + 512);               // 512 floats
    ulonglong2* wsm = (ulonglong2*)(smem + 2560);     // [4][512]

    int tid = threadIdx.x;
    const ulonglong2* wr = reinterpret_cast<const ulonglong2*>(whh + (size_t)tid * 128);
    ulonglong2 w[28];
#pragma unroll
    for (int q = 0; q < 28; q++) w[q] = wr[q];
#pragma unroll
    for (int q = 0; q < 4; q++) wsm[q * 512 + tid] = wr[28 + q];

    if (tid < 128) h_sh[tid] = 0.0f;
    float c = 0.0f;
    __syncthreads();

    const ulonglong2* h2 = reinterpret_cast<const ulonglong2*>(h_sh);
    int nch = (T + CS - 1) / CS;

    for (int ci = 0; ci < nch; ci++) {
        int t0 = ci * CS, t1 = min(T, t0 + CS);
        if (rdy) {
            if (tid == 0) { while (ld_acq(&rdy[ci]) == 0) __nanosleep(64); }
            __syncthreads();
        }
        float gxv = __ldg(gx + (size_t)t0 * 512 + tid);

        for (int t = t0; t < t1; t++) {
            float gxn = 0.0f;
            if (t + 1 < t1) gxn = __ldg(gx + (size_t)(t + 1) * 512 + tid);

            ull a0 = 0ULL, a1 = 0ULL, a2 = 0ULL, a3 = 0ULL;
#pragma unroll
            for (int q = 0; q < 28; q++) {
                ulonglong2 hv = h2[q];
                if (q & 1) { a2 = ffma2(w[q].x, hv.x, a2); a3 = ffma2(w[q].y, hv.y, a3); }
                else       { a0 = ffma2(w[q].x, hv.x, a0); a1 = ffma2(w[q].y, hv.y, a1); }
            }
#pragma unroll
            for (int q = 0; q < 4; q++) {
                ulonglong2 hv = h2[28 + q];
                ulonglong2 wv = wsm[q * 512 + tid];
                if (q & 1) { a2 = ffma2(wv.x, hv.x, a2); a3 = ffma2(wv.y, hv.y, a3); }
                else       { a0 = ffma2(wv.x, hv.x, a0); a1 = ffma2(wv.y, hv.y, a1); }
            }
            float2 f0 = upk(a0), f1 = upk(a1), f2 = upk(a2), f3 = upk(a3);
            float g = gxv + (((f0.x + f0.y) + (f1.x + f1.y)) + ((f2.x + f2.y) + (f3.x + f3.y)));
            g_sh[tid] = g;
            gxv = gxn;
            __syncthreads();               // all dots done; h_sh may now be overwritten

            if (tid < 128) {
                float ig = g_sh[tid];
                float fg = g_sh[tid + 128];
                float gg = g_sh[tid + 256];
                float og = g_sh[tid + 384];
                c = fast_sig(fg) * c + fast_sig(ig) * fast_tanh(gg);
                float h = fast_sig(og) * fast_tanh(c);
                h_sh[tid] = h;
                hs[(size_t)t * 128 + tid] = h;
            }
            __syncthreads();               // new h visible to all
        }

        if (prog && tid == 0) { __threadfence(); st_rel(prog, t1); }
    }

    if (tid < 128) { outH[tid] = h_sh[tid]; outC[tid] = c; }
}

// ---------------- pipelined LSTM kernel: CTA0=layer0, CTA1=layer1, CTA2-3=gx1 workers ---
__global__ void __launch_bounds__(512, 1) k_pipe(
    const float* __restrict__ gx0,
    const float* __restrict__ whh0, const float* __restrict__ whh1,
    const float* __restrict__ wih1,
    const float* __restrict__ bih1, const float* __restrict__ bhh1,
    float* outH, float* outC, int T)
{
    extern __shared__ char smem[];
    float* p_hs0 = g_hs0;
    float* p_hs1 = g_hs1;
    float* p_gx1 = g_gx1;
    int role = blockIdx.x;

    if (role == 0) {
        lstm_seq(gx0, whh0, p_hs0, outH, outC, T, &g_prog0, nullptr, smem);
    } else if (role == 1) {
        lstm_seq(p_gx1, whh1, p_hs1, outH + 128, outC + 128, T, nullptr, g_rdy, smem);
    } else {
        int widx = role - 2;
        int nch = (T + CS - 1) / CS;
        for (int ci = widx; ci < nch; ci += 2) {
            int t0 = ci * CS, t1 = min(T, t0 + CS);
            if (threadIdx.x == 0) { while (ld_acq(&g_prog0) < t1) __nanosleep(64); }
            __syncthreads();
            gemm_chunk(p_hs0 + (size_t)t0 * 128, t1 - t0, wih1, bih1, bhh1,
                       p_gx1 + (size_t)t0 * 512, (float*)smem);
            __syncthreads();
            if (threadIdx.x == 0) { __threadfence(); st_rel(&g_rdy[ci], 1); }
        }
    }
}

// ---------------- edge head ----------------
__global__ void __launch_bounds__(256) k_edge(
    const float* __restrict__ hs1, const float* __restrict__ ef,
    const float* __restrict__ eW, const float* __restrict__ eb,
    const float* __restrict__ cW, const float* __restrict__ cb,
    float* __restrict__ pred, float* __restrict__ osrc, float* __restrict__ odst, int E)
{
    __shared__ __align__(16) float sW[32 * 128];
    __shared__ __align__(16) float scW[384];
    __shared__ __align__(16) float seb[128];
    int tid = threadIdx.x;
    for (int i = tid; i < 32 * 128; i += 256) sW[i] = eW[i];
    for (int i = tid; i < 384; i += 256) scW[i] = cW[i];
    if (tid < 128) seb[tid] = eb[tid];
    __syncthreads();

    int warp = tid >> 5, lane = tid & 31;
    int e = blockIdx.x * 8 + warp;
    if (e >= E) return;

    int s = g_src[e], d = g_dst[e];
    float4 sv = *(const float4*)(hs1 + (size_t)s * 128 + lane * 4);
    float4 dv = *(const float4*)(hs1 + (size_t)d * 128 + lane * 4);
    float efv = ef[(size_t)e * 32 + lane];

    float4 emb = *(const float4*)(seb + lane * 4);
#pragma unroll
    for (int k = 0; k < 32; k++) {
        float fk = __shfl_sync(0xffffffffu, efv, k);
        float4 wv = *(const float4*)(sW + k * 128 + lane * 4);
        emb.x += fk * wv.x; emb.y += fk * wv.y; emb.z += fk * wv.z; emb.w += fk * wv.w;
    }

    float4 c0 = *(const float4*)(scW + lane * 4);
    float4 c1 = *(const float4*)(scW + 128 + lane * 4);
    float4 c2 = *(const float4*)(scW + 256 + lane * 4);
    float p = sv.x * c0.x + sv.y * c0.y + sv.z * c0.z + sv.w * c0.w
            + dv.x * c1.x + dv.y * c1.y + dv.z * c1.z + dv.w * c1.w
            + emb.x * c2.x + emb.y * c2.y + emb.z * c2.z + emb.w * c2.w;
#pragma unroll
    for (int off = 16; off; off >>= 1) p += __shfl_xor_sync(0xffffffffu, p, off);
    if (lane == 0) pred[e] = p + cb[0];

    *(float4*)(osrc + (size_t)e * 128 + lane * 4) = sv;
    *(float4*)(odst + (size_t)e * 128 + lane * 4) = dv;
}

// ---------------- launch ----------------
extern "C" void kernel_launch(void* const* d_in, const int* in_sizes, int n_in,
                              void* d_out, int out_size)
{
    const float* x    = (const float*)d_in[0];
    const void*  ei   = d_in[1];
    const float* ef   = (const float*)d_in[2];
    const float* W1   = (const float*)d_in[3];
    const float* b1   = (const float*)d_in[4];
    const float* W2   = (const float*)d_in[5];
    const float* b2   = (const float*)d_in[6];
    const float* wih0 = (const float*)d_in[7];
    const float* whh0 = (const float*)d_in[8];
    const float* bih0 = (const float*)d_in[9];
    const float* bhh0 = (const float*)d_in[10];
    const float* wih1 = (const float*)d_in[11];
    const float* whh1 = (const float*)d_in[12];
    const float* bih1 = (const float*)d_in[13];
    const float* bhh1 = (const float*)d_in[14];
    const float* eW   = (const float*)d_in[15];
    const float* eb   = (const float*)d_in[16];
    const float* cW   = (const float*)d_in[17];
    const float* cb   = (const float*)d_in[18];

    int N = in_sizes[0] / 128;
    int E = in_sizes[1] / 2;
    float* out = (float*)d_out;

    float *p_xw, *p_h, *p_hs1, *p_gx, *p_dinv;
    cudaGetSymbolAddress((void**)&p_xw,  g_xw);
    cudaGetSymbolAddress((void**)&p_h,   g_h);
    cudaGetSymbolAddress((void**)&p_hs1, g_hs1);
    cudaGetSymbolAddress((void**)&p_gx,  g_gx);
    cudaGetSymbolAddress((void**)&p_dinv, g_dinv);

    static int smem_set = 0;
    if (!smem_set) {
        cudaFuncSetAttribute(k_pipe, cudaFuncAttributeMaxDynamicSharedMemorySize, 36864);
        smem_set = 1;
    }

    // edge index normalize + degree (fused) + counter resets
    k_detect<<<1, 32>>>((const int*)ei);
    k_init<<<(N * 128 + 255) / 256, 256>>>(N);
    k_convert<<<(E + 255) / 256, 256>>>(ei, E, N);
    k_rsqrt<<<(N + 255) / 256, 256>>>(N);

    dim3 g128(128 / 64, (N + 63) / 64);
    dim3 g512(512 / 64, (N + 63) / 64);

    // GCN conv 1: y = (x@W1) prescaled by dinv; scatter pure adds; finish scales by dinv_d
    k_gemm<0><<<g128, 256>>>(x, W1, nullptr, nullptr, p_dinv, p_xw, N, 128);
    k_scatter<<<((size_t)E * 32 + 255) / 256, 256>>>(p_xw, E);
    k_finish<<<(N * 128 + 255) / 256, 256>>>(p_xw, b1, p_h, N, 1);

    // GCN conv 2
    k_gemm<0><<<g128, 256>>>(p_h, W2, nullptr, nullptr, p_dinv, p_xw, N, 128);
    k_scatter<<<((size_t)E * 32 + 255) / 256, 256>>>(p_xw, E);
    k_finish<<<(N * 128 + 255) / 256, 256>>>(p_xw, b2, p_h, N, 0);

    // output layout: pred[E] | hn[2*128] | cn[2*128] | src[E*128] | dst[E*128]
    float* out_hn  = out + E;
    float* out_cn  = out + E + 256;
    float* out_src = out + E + 512;
    float* out_dst = out_src + (size_t)E * 128;

    // layer0 gate-input GEMM (full, parallel)
    k_gemm<1><<<g512, 256>>>(p_h, wih0, bih0, bhh0, nullptr, p_gx, N, 512);

    // pipelined LSTM: layer0 + layer1 + 2 gx1-GEMM workers, one launch (grid=4)
    k_pipe<<<4, 512, 36864>>>(p_gx, whh0, whh1, wih1, bih1, bhh1, out_hn, out_cn, N);

    // edge head
    k_edge<<<(E + 7) / 8, 256>>>(p_hs1, ef, eW, eb, cW, cb, out, out_src, out_dst, E);
}